// round 1
// baseline (speedup 1.0000x reference)
#include <cuda_runtime.h>
#include <math.h>

#define K_CODES 2048
#define DDIM    512
#define BDIM    64
#define TDIM    256
#define N_ROWS  (BDIM*TDIM)        /* 16384 */
#define QN      (BDIM*DDIM*TDIM)   /* 8388608 */
#define OUT_LOSS 0
#define OUT_Q    1
#define OUT_PERP (1+QN)
#define OUT_IDX  (2+QN)

/* dynamic smem layout (floats):
   A_s   [512][64]      0      .. 32768
   Wt_s  [64][68]       32768  .. 37120   (k-major, pad 68)
   dist_s[64][65]       37120  .. 41280
   fsq_s [64]           41280  .. 41344
   wsq_s [64]           41344  .. 41408
   red_s [8]            41408  .. 41416
*/
#define SMEM_FLOATS 41416

__device__ float g_wsq[K_CODES];
__device__ int   g_counts[K_CODES];
__device__ float g_partials[256];

__global__ void init_kernel() {
    int i = blockIdx.x * blockDim.x + threadIdx.x;
    if (i < K_CODES) g_counts[i] = 0;
}

__global__ void wsq_kernel(const float* __restrict__ W) {
    int warp = (blockIdx.x * blockDim.x + threadIdx.x) >> 5;
    int lane = threadIdx.x & 31;
    if (warp >= K_CODES) return;
    const float* row = W + (size_t)warp * DDIM;
    float s = 0.f;
    #pragma unroll
    for (int d = lane; d < DDIM; d += 32) { float v = row[d]; s += v * v; }
    #pragma unroll
    for (int o = 16; o > 0; o >>= 1) s += __shfl_xor_sync(0xffffffffu, s, o);
    if (lane == 0) g_wsq[warp] = s;
}

__global__ __launch_bounds__(256, 1)
void vq_main(const float* __restrict__ x, const float* __restrict__ W,
             float* __restrict__ out) {
    extern __shared__ float sm[];
    float* A_s    = sm;                 // [512][64]  k-major
    float* Wt_s   = sm + 32768;         // [64][68]   k-major
    float* dist_s = sm + 37120;         // [64][65]
    float* fsq_s  = sm + 41280;         // [64]
    float* wsq_s  = sm + 41344;         // [64]
    float* red_s  = sm + 41408;         // [8]

    const int tid = threadIdx.x;
    const int tx  = tid & 15;
    const int ty  = tid >> 4;
    const int gr0 = blockIdx.x * 64;    // first global row of this block
    const int b   = gr0 >> 8;           // batch index (64 rows stay in one b)
    const int t0  = gr0 & 255;          // time offset

    const float* xb = x + (size_t)b * (DDIM * TDIM) + t0;

    // ---- load A tile: A_s[d][r] = x[b][d][t0+r] (coalesced over r) ----
    for (int i = tid; i < DDIM * 64; i += 256) {
        int d = i >> 6, r = i & 63;
        A_s[d * 64 + r] = xb[(size_t)d * TDIM + r];
    }
    __syncthreads();

    // ---- fsq per row ----
    if (tid < 64) {
        float s = 0.f;
        for (int d = 0; d < DDIM; d++) { float v = A_s[d * 64 + tid]; s += v * v; }
        fsq_s[tid] = s;
    }

    // running top-3 (row-owner threads tid<64, row = tid)
    float bd0 = INFINITY, bd1 = INFINITY, bd2 = INFINITY;
    int   bi0 = 0, bi1 = 0, bi2 = 0;

    const int lc = tid & 63;            // code this thread loads
    const int lk = (tid >> 6) * 16;     // k-offset this thread loads

    for (int p = 0; p < 32; p++) {
        const int c0 = p * 64;
        if (tid < 64) wsq_s[tid] = g_wsq[c0 + tid];

        float acc[4][4];
        #pragma unroll
        for (int i = 0; i < 4; i++)
            #pragma unroll
            for (int j = 0; j < 4; j++) acc[i][j] = 0.f;

        for (int kk = 0; kk < 8; kk++) {
            const int k0 = kk * 64;
            __syncthreads();   // Wt_s free (also: owners finished prior scan, wsq ready)
            // load W chunk: 64 codes x 64 k, store k-major, conflict-free STS
            {
                const float4* wsrc =
                    (const float4*)(W + (size_t)(c0 + lc) * DDIM + k0 + lk);
                #pragma unroll
                for (int j = 0; j < 4; j++) {
                    float4 v = wsrc[j];
                    int kb = lk + j * 4;
                    Wt_s[(kb + 0) * 68 + lc] = v.x;
                    Wt_s[(kb + 1) * 68 + lc] = v.y;
                    Wt_s[(kb + 2) * 68 + lc] = v.z;
                    Wt_s[(kb + 3) * 68 + lc] = v.w;
                }
            }
            __syncthreads();
            #pragma unroll 16
            for (int k = 0; k < 64; k++) {
                float4 a  = *(const float4*)(A_s + (size_t)(k0 + k) * 64 + ty * 4);
                float4 bb = *(const float4*)(Wt_s + k * 68 + tx * 4);
                acc[0][0] += a.x * bb.x; acc[0][1] += a.x * bb.y;
                acc[0][2] += a.x * bb.z; acc[0][3] += a.x * bb.w;
                acc[1][0] += a.y * bb.x; acc[1][1] += a.y * bb.y;
                acc[1][2] += a.y * bb.z; acc[1][3] += a.y * bb.w;
                acc[2][0] += a.z * bb.x; acc[2][1] += a.z * bb.y;
                acc[2][2] += a.z * bb.z; acc[2][3] += a.z * bb.w;
                acc[3][0] += a.w * bb.x; acc[3][1] += a.w * bb.y;
                acc[3][2] += a.w * bb.z; acc[3][3] += a.w * bb.w;
            }
        }

        // write dists, replicating reference rounding: (fsq + wsq) - (2*dot)
        #pragma unroll
        for (int i = 0; i < 4; i++) {
            int ry = ty * 4 + i;
            float fs = fsq_s[ry];
            #pragma unroll
            for (int j = 0; j < 4; j++) {
                int cx = tx * 4 + j;
                float t1 = __fadd_rn(fs, wsq_s[cx]);
                float dd = __fadd_rn(t1, -__fmul_rn(2.0f, acc[i][j]));
                dist_s[ry * 65 + cx] = dd;
            }
        }
        __syncthreads();

        if (tid < 64) {
            #pragma unroll 8
            for (int c = 0; c < 64; c++) {
                float dv = dist_s[tid * 65 + c];
                int code = c0 + c;
                if (dv < bd0) {
                    bd2 = bd1; bi2 = bi1; bd1 = bd0; bi1 = bi0; bd0 = dv; bi0 = code;
                } else if (dv < bd1) {
                    bd2 = bd1; bi2 = bi1; bd1 = dv; bi1 = code;
                } else if (dv < bd2) {
                    bd2 = dv; bi2 = code;
                }
            }
        }
        // next panel's first __syncthreads separates scan from dist_s overwrite
    }
    __syncthreads();

    int* idx_s = (int*)dist_s;   // safe reuse after barrier
    if (tid < 64) {
        idx_s[tid * 3 + 0] = bi0;
        idx_s[tid * 3 + 1] = bi1;
        idx_s[tid * 3 + 2] = bi2;
        atomicAdd(&g_counts[bi0], 1);
        atomicAdd(&g_counts[bi1], 1);
        atomicAdd(&g_counts[bi2], 1);
        out[OUT_IDX + gr0 + tid] = (float)bi2;   // encoding_indices = 3rd nearest
    }
    __syncthreads();

    // ---- quantized output + MSE partial ----
    float mse = 0.f;
    for (int it = 0; it < 128; it++) {
        int lin = it * 256 + tid;
        int r = lin & 63, d = lin >> 6;
        int j0 = idx_s[r * 3 + 0];
        int j1 = idx_s[r * 3 + 1];
        int j2 = idx_s[r * 3 + 2];
        float q = (W[(size_t)j0 * DDIM + d] +
                   W[(size_t)j1 * DDIM + d] +
                   W[(size_t)j2 * DDIM + d]) * (1.0f / 3.0f);
        out[OUT_Q + (size_t)(b * DDIM + d) * TDIM + t0 + r] = q;
        float df = q - A_s[d * 64 + r];
        mse += df * df;
    }
    #pragma unroll
    for (int o = 16; o > 0; o >>= 1) mse += __shfl_xor_sync(0xffffffffu, mse, o);
    if ((tid & 31) == 0) red_s[tid >> 5] = mse;
    __syncthreads();
    if (tid == 0) {
        float s = 0.f;
        #pragma unroll
        for (int i = 0; i < 8; i++) s += red_s[i];
        g_partials[blockIdx.x] = s;   // deterministic: fixed slot per block
    }
}

__global__ void finalize_kernel(float* __restrict__ out) {
    __shared__ float red[256];
    int tid = threadIdx.x;
    // loss = 1.25 * mean((q - x)^2)   (e_latent == q_latent numerically)
    red[tid] = g_partials[tid];
    __syncthreads();
    for (int s = 128; s > 0; s >>= 1) {
        if (tid < s) red[tid] += red[tid + s];
        __syncthreads();
    }
    if (tid == 0) out[OUT_LOSS] = 1.25f * (red[0] / (float)QN);
    __syncthreads();
    // perplexity
    float e = 0.f;
    for (int k = tid; k < K_CODES; k += 256) {
        float pr = (float)g_counts[k] * (1.0f / (float)N_ROWS);
        e += pr * logf(pr + 1e-10f);
    }
    red[tid] = e;
    __syncthreads();
    for (int s = 128; s > 0; s >>= 1) {
        if (tid < s) red[tid] += red[tid + s];
        __syncthreads();
    }
    if (tid == 0) out[OUT_PERP] = expf(-red[0]);
}

extern "C" void kernel_launch(void* const* d_in, const int* in_sizes, int n_in,
                              void* d_out, int out_size) {
    const float* x = (const float*)d_in[0];
    const float* W = (const float*)d_in[1];
    float* out = (float*)d_out;
    (void)in_sizes; (void)n_in; (void)out_size;

    cudaFuncSetAttribute(vq_main, cudaFuncAttributeMaxDynamicSharedMemorySize,
                         SMEM_FLOATS * 4);

    init_kernel<<<8, 256>>>();
    wsq_kernel<<<256, 256>>>(W);
    vq_main<<<256, 256, SMEM_FLOATS * 4>>>(x, W, out);
    finalize_kernel<<<1, 256>>>(out);
}